// round 16
// baseline (speedup 1.0000x reference)
#include <cuda_runtime.h>
#include <cuda_bf16.h>
#include <math.h>
#include <stdint.h>

// Shapes (fixed for this problem)
#define BATCH 16
#define SEQL  128
#define DIM   768
#define NH1   770
#define NOUT  40
#define NPAIR 3405
#define LP1   129     // L+1 rows per batch in hidden_states
#define PST   772     // padded row stride for P/Q (float4-aligned)

// Scratch: P = X @ W1i, Q = X @ W1j + b1 (bias folded; pad cols zero).
__device__ float g_P[(size_t)BATCH * SEQL * PST + 64];
__device__ float g_Q[(size_t)BATCH * SEQL * PST + 64];
// Precomputed split-bf16 W2 tiles: [chunk(25)][n(48)][kword(16)].
__device__ uint32_t g_W2h[25 * 768];
__device__ uint32_t g_W2l[25 * 768];
// Precomputed split-bf16 A (hidden rows): [row(2048)][kword(384)].
__device__ __align__(16) uint32_t g_Ah[2048 * 384];
__device__ __align__(16) uint32_t g_Al[2048 * 384];
// Precomputed split-bf16 B (W1 halves, transposed): [z(2)][n(864 pad)][kword(384)].
__device__ __align__(16) uint32_t g_Bh[2 * 864 * 384];
__device__ __align__(16) uint32_t g_Bl[2 * 864 * 384];

// ---------------------------------------------------------------------------
// Helpers
// ---------------------------------------------------------------------------
__device__ __forceinline__ uint32_t smem_u32(const void* p) {
    uint32_t a;
    asm("{ .reg .u64 t; cvta.to.shared.u64 t, %1; cvt.u32.u64 %0, t; }" : "=r"(a) : "l"(p));
    return a;
}
#define LDM_X4(r0, r1, r2, r3, addr) \
    asm volatile("ldmatrix.sync.aligned.m8n8.x4.shared.b16 {%0,%1,%2,%3}, [%4];" \
                 : "=r"(r0), "=r"(r1), "=r"(r2), "=r"(r3) : "r"(addr))

__device__ __forceinline__ void mma_bf16(float* d, const uint32_t* a,
                                         uint32_t b0, uint32_t b1) {
    asm volatile(
        "mma.sync.aligned.m16n8k16.row.col.f32.bf16.bf16.f32 "
        "{%0,%1,%2,%3}, {%4,%5,%6,%7}, {%8,%9}, {%0,%1,%2,%3};\n"
        : "+f"(d[0]), "+f"(d[1]), "+f"(d[2]), "+f"(d[3])
        : "r"(a[0]), "r"(a[1]), "r"(a[2]), "r"(a[3]), "r"(b0), "r"(b1));
}
// Fast packed split: x = hi + lo, both bf16 (RN), 6 instructions per 2 values.
// hw = {hi: bf16(x1), lo: bf16(x0)}; reconstruction via bit placement.
__device__ __forceinline__ void split2(float x0, float x1, uint32_t& hw, uint32_t& lw) {
    asm("cvt.rn.bf16x2.f32 %0, %1, %2;" : "=r"(hw) : "f"(x1), "f"(x0));
    float h0 = __uint_as_float(hw << 16);
    float h1 = __uint_as_float(hw & 0xffff0000u);
    float l0 = x0 - h0;
    float l1 = x1 - h1;
    asm("cvt.rn.bf16x2.f32 %0, %1, %2;" : "=r"(lw) : "f"(l1), "f"(l0));
}

// ---------------------------------------------------------------------------
// Kernel 0 (merged prep): block-range dispatch.
// ---------------------------------------------------------------------------
#define PREP_A_BLKS  3072
#define PREP_B_BLKS  672
#define PREP_W2_BLKS 75

__global__ void prep_all(const float* __restrict__ hidden,
                         const float* __restrict__ W1,
                         const float* __restrict__ W2) {
    __shared__ float ts[32][65];
    const int blk = blockIdx.x;
    const int tid = threadIdx.x;

    if (blk < PREP_A_BLKS) {
        int idx = blk * 256 + tid;
        int row = idx / 384;
        int kw  = idx - row * 384;
        int bb = row >> 7, t = row & 127;
        const float* src = hidden + ((size_t)bb * LP1 + t + 1) * DIM + kw * 2;
        float2 v = *(const float2*)src;
        uint32_t hw, lw;
        split2(v.x, v.y, hw, lw);
        g_Ah[idx] = hw;
        g_Al[idx] = lw;
    } else if (blk < PREP_A_BLKS + PREP_B_BLKS) {
        int bid = blk - PREP_A_BLKS;
        int z   = bid / 336;
        int t2  = bid - z * 336;
        int kt  = t2 % 24;
        int nt  = t2 / 24;
        int k0  = kt * 32;
        int n0  = nt * 64;
        const float* W = W1 + (size_t)z * DIM * NH1;

        int nx = tid & 63;
        int ky0 = tid >> 6;
        #pragma unroll
        for (int s = 0; s < 8; s++) {
            int ky = ky0 + 4 * s;
            int n  = n0 + nx;
            ts[ky][nx] = (n < NH1) ? W[(size_t)(k0 + ky) * NH1 + n] : 0.f;
        }
        __syncthreads();
        int kx  = tid & 15;
        int ny0 = tid >> 4;
        #pragma unroll
        for (int s = 0; s < 4; s++) {
            int ny = ny0 + 16 * s;
            int n  = n0 + ny;
            if (n < 864) {
                uint32_t hw, lw;
                split2(ts[2*kx][ny], ts[2*kx+1][ny], hw, lw);
                size_t gidx = ((size_t)z * 864 + n) * 384 + kt * 16 + kx;
                g_Bh[gidx] = hw;
                g_Bl[gidx] = lw;
            }
        }
    } else {
        int idx = (blk - PREP_A_BLKS - PREP_B_BLKS) * 256 + tid;
        if (idx >= 25 * 768) return;
        int ch = idx / 768, rem = idx - ch * 768;
        int n = rem >> 4, kw = rem & 15;
        int k = ch * 32 + kw * 2;
        float x0 = 0.f, x1 = 0.f;
        if (n < NOUT) {
            if (k     < NH1) x0 = W2[(size_t)k       * NOUT + n];
            if (k + 1 < NH1) x1 = W2[(size_t)(k + 1) * NOUT + n];
        }
        uint32_t hw, lw;
        split2(x0, x1, hw, lw);
        g_W2h[idx] = hw;
        g_W2l[idx] = lw;
    }
}

// ---------------------------------------------------------------------------
// Kernel 1: 2048 x 864 x 768 GEMM, bf16 m16n8k16 + ldmatrix, pre-split
// inputs, 128x96 tile, 288-block wave. z==1 epilogue folds b1 into Q.
// ---------------------------------------------------------------------------
#define G_BK  32
#define G_NKT (DIM / G_BK)   // 24
#define RS    80             // smem row stride in bytes
#define AHI_O 0
#define ALO_O (128 * RS)
#define BHI_O (2 * 128 * RS)
#define BLO_O (BHI_O + 96 * RS)

__global__ __launch_bounds__(256, 2)
void gemm1_mma(const float* __restrict__ bias1) {
    __shared__ __align__(16) unsigned char smbuf[BLO_O + 96 * RS];
    const uint32_t sb = smem_u32(smbuf);

    const int tid = threadIdx.x;
    const int wid = tid >> 5;
    const int lid = tid & 31;
    const int grp = lid >> 2;
    const int tig = lid & 3;
    const int wm  = wid & 3;
    const int wn  = wid >> 2;

    const int n0 = blockIdx.x * 96;
    const int m0 = blockIdx.y * 128;
    const int z  = blockIdx.z;
    float* Cout = (z == 0) ? g_P : g_Q;

    float acc[2][6][4];
    #pragma unroll
    for (int mf = 0; mf < 2; mf++)
        #pragma unroll
        for (int nf = 0; nf < 6; nf++)
            #pragma unroll
            for (int c = 0; c < 4; c++) acc[mf][nf][c] = 0.f;

    const int a_q = tid & 3;
    const int a_r = tid >> 2;
    const int b_w8 = tid & 7;
    const int b_r  = tid >> 3;
    const size_t bbase = ((size_t)z * 864 + n0) * 384;

    const int a_lrow = lid & 15;
    const int a_lk   = (lid >> 4) << 3;
    const int b_lrow = (lid & 7) + ((lid >> 4) << 3);
    const int b_lk   = ((lid >> 3) & 1) << 3;

    for (int kt = 0; kt < G_NKT; kt++) {
        const int kw0 = kt * 16;
        #pragma unroll
        for (int p = 0; p < 2; p++) {
            const int row = a_r + 64 * p;
            const size_t gidx = (size_t)(m0 + row) * 384 + kw0 + a_q * 4;
            uint4 h = *(const uint4*)(g_Ah + gidx);
            uint4 l = *(const uint4*)(g_Al + gidx);
            *(uint4*)(smbuf + AHI_O + row * RS + a_q * 16) = h;
            *(uint4*)(smbuf + ALO_O + row * RS + a_q * 16) = l;
        }
        #pragma unroll
        for (int p = 0; p < 3; p++) {
            const int row = b_r + 32 * p;
            const size_t gidx = bbase + (size_t)row * 384 + kw0 + b_w8 * 2;
            uint2 h = *(const uint2*)(g_Bh + gidx);
            uint2 l = *(const uint2*)(g_Bl + gidx);
            *(uint2*)(smbuf + BHI_O + row * RS + b_w8 * 8) = h;
            *(uint2*)(smbuf + BLO_O + row * RS + b_w8 * 8) = l;
        }
        __syncthreads();

        #pragma unroll
        for (int h = 0; h < 2; h++) {
            const int ks = h * 16;
            uint32_t ah[2][4], al[2][4];
            #pragma unroll
            for (int mf = 0; mf < 2; mf++) {
                const uint32_t ad = sb + (wm * 32 + mf * 16 + a_lrow) * RS
                                       + (ks + a_lk) * 2;
                LDM_X4(ah[mf][0], ah[mf][1], ah[mf][2], ah[mf][3], ad + AHI_O);
                LDM_X4(al[mf][0], al[mf][1], al[mf][2], al[mf][3], ad + ALO_O);
            }
            #pragma unroll
            for (int p = 0; p < 3; p++) {
                const uint32_t bd = sb + (wn * 48 + p * 16 + b_lrow) * RS
                                       + (ks + b_lk) * 2;
                uint32_t bh[4], bl[4];
                LDM_X4(bh[0], bh[1], bh[2], bh[3], bd + BHI_O);
                LDM_X4(bl[0], bl[1], bl[2], bl[3], bd + BLO_O);
                #pragma unroll
                for (int q = 0; q < 2; q++) {
                    const int nf = 2 * p + q;
                    #pragma unroll
                    for (int mf = 0; mf < 2; mf++) {
                        mma_bf16(acc[mf][nf], ah[mf], bh[2*q], bh[2*q+1]);
                        mma_bf16(acc[mf][nf], ah[mf], bl[2*q], bl[2*q+1]);
                        mma_bf16(acc[mf][nf], al[mf], bh[2*q], bh[2*q+1]);
                    }
                }
            }
        }
        __syncthreads();
    }

    // Epilogue. z==1 folds b1 (guarded: pad cols 770/771 stay exactly 0).
    #pragma unroll
    for (int mf = 0; mf < 2; mf++) {
        const int row = m0 + wm * 32 + mf * 16 + grp;
        #pragma unroll
        for (int nf = 0; nf < 6; nf++) {
            const int nn = n0 + wn * 48 + nf * 8 + tig * 2;
            if (nn + 1 < PST) {
                float ba0 = 0.f, ba1 = 0.f;
                if (z == 1) {
                    if (nn     < NH1) ba0 = bias1[nn];
                    if (nn + 1 < NH1) ba1 = bias1[nn + 1];
                }
                float* p0 = Cout + (size_t)row * PST + nn;
                float* p1 = Cout + (size_t)(row + 8) * PST + nn;
                *(float2*)p0 = make_float2(acc[mf][nf][0] + ba0, acc[mf][nf][1] + ba1);
                *(float2*)p1 = make_float2(acc[mf][nf][2] + ba0, acc[mf][nf][3] + ba1);
            }
        }
    }
}

// ---------------------------------------------------------------------------
// Kernel 2 (R12 skeleton + fast split + b1 pre-folded): tensorized span head,
// double-buffered. Ht = relu(P[vi] + Q'[vj] + ind*w1c) split bf16;
// logits = Ht @ W2 (mma m16n8k16, 3-term) + b2; fused log_softmax.
// ---------------------------------------------------------------------------
#define SP_NCH   25
#define SP_STAGE 28160
#define AHT_HI   0
#define AHT_LO   10240
#define W2H_O    20480
#define W2L_O    24320
#define WS1C_O   (2 * SP_STAGE)        // 56320
#define SRI_O    (WS1C_O + 832 * 4)    // 59648
#define SRJ_O    (SRI_O + 512)
#define SIND_O   (SRJ_O + 512)
#define SP_DSM   (SIND_O + 512)        // 61184

__global__ __launch_bounds__(256, 2)
void span_head_tensor(const float* __restrict__ W1,
                      const float* __restrict__ bias2,
                      const int* __restrict__ spans, float* __restrict__ out) {
    extern __shared__ __align__(16) unsigned char dsm[];
    const uint32_t sb = smem_u32(dsm);
    float* ws1c = (float*)(dsm + WS1C_O);
    int*   s_ri = (int*)(dsm + SRI_O);
    int*   s_rj = (int*)(dsm + SRJ_O);
    float* s_in = (float*)(dsm + SIND_O);

    const int b   = blockIdx.y;
    const int p0  = blockIdx.x * 128;
    const int tid = threadIdx.x;
    const int wid = tid >> 5;
    const int lid = tid & 31;
    const int grp = lid >> 2;
    const int tig = lid & 3;

    const float* w1c = W1 + (size_t)2 * DIM * NH1;

    for (int idx = tid; idx < 832; idx += 256)
        ws1c[idx] = (idx < NH1) ? w1c[idx] : 0.f;
    if (tid < 128) {
        int p  = p0 + tid;
        int pc = (p < NPAIR) ? p : (NPAIR - 1);
        int i, j;
        if (pc < 2970) {
            i = pc / 30;
            j = i + (pc - 30 * i);
        } else {
            int q = pc - 2970;
            int d = (int)(29.5f - sqrtf(870.25f - 2.0f * (float)q));
            while ((d + 1) * (58 - d) / 2 <= q) d++;
            while (d * (59 - d) / 2 > q) d--;
            i = 99 + d;
            j = i + (q - d * (59 - d) / 2);
        }
        float ind = 0.f;
        if (p < NPAIR) {
            int s = spans[b*2 + 0];
            int e = spans[b*2 + 1];
            if (i == s && j == e)      ind = 2.f;
            else if (i >= s && j <= e) ind = 1.f;
        }
        s_ri[tid] = (b * SEQL + i) * PST;
        s_rj[tid] = (b * SEQL + j) * PST;
        s_in[tid] = ind;
    }
    __syncthreads();

    const int g_kq = tid & 7;
    const int g_r0 = tid >> 3;
    int   ri[4], rj[4];
    float indv[4];
    #pragma unroll
    for (int w = 0; w < 4; w++) {
        int r = g_r0 + w * 32;
        ri[w] = s_ri[r]; rj[w] = s_rj[r]; indv[w] = s_in[r];
    }

    const int a_lrow = lid & 15;
    const int a_lk   = (lid >> 4) << 3;
    const int b_lrow = (lid & 7) + ((lid >> 4) << 3);
    const int b_lk   = ((lid >> 3) & 1) << 3;

    float acc[5][4];
    #pragma unroll
    for (int nf = 0; nf < 5; nf++)
        #pragma unroll
        for (int c = 0; c < 4; c++) acc[nf][c] = 0.f;

    {   // prologue: stage 0 (chunk 0)
        const int kb = g_kq * 4;
        float4 c1 = *(const float4*)(ws1c + kb);
        #pragma unroll
        for (int w = 0; w < 4; w++) {
            int r = g_r0 + w * 32;
            float4 p4 = *(const float4*)(g_P + ri[w] + kb);
            float4 q4 = *(const float4*)(g_Q + rj[w] + kb);
            float v0 = fmaxf(fmaf(indv[w], c1.x, p4.x + q4.x), 0.f);
            float v1 = fmaxf(fmaf(indv[w], c1.y, p4.y + q4.y), 0.f);
            float v2 = fmaxf(fmaf(indv[w], c1.z, p4.z + q4.z), 0.f);
            float v3 = fmaxf(fmaf(indv[w], c1.w, p4.w + q4.w), 0.f);
            uint32_t hw0, lw0, hw1, lw1;
            split2(v0, v1, hw0, lw0);
            split2(v2, v3, hw1, lw1);
            uint32_t ro = r * RS + g_kq * 8;
            *(uint2*)(dsm + AHT_HI + ro) = make_uint2(hw0, hw1);
            *(uint2*)(dsm + AHT_LO + ro) = make_uint2(lw0, lw1);
        }
        #pragma unroll
        for (int u = 0; u < 3; u++) {
            int w = tid + 256 * u;
            int n = w >> 4, kw = w & 15;
            *(uint32_t*)(dsm + W2H_O + n * RS + kw * 4) = g_W2h[w];
            *(uint32_t*)(dsm + W2L_O + n * RS + kw * 4) = g_W2l[w];
        }
    }
    __syncthreads();

    for (int ch = 0; ch < SP_NCH; ch++) {
        const int cur = ch & 1;
        const bool has_next = (ch + 1 < SP_NCH);
        const int kb_n = (ch + 1) * 32 + g_kq * 4;
        unsigned char* nxt = dsm + ((ch + 1) & 1) * SP_STAGE;

        // 1) prefetch chunk ch+1: P/Q into regs; W2 LDG->STS into nxt (safe:
        //    prior barrier retired all reads of nxt).
        float4 pp[4], qq[4];
        if (has_next) {
            if (kb_n < PST) {
                #pragma unroll
                for (int w = 0; w < 4; w++) {
                    pp[w] = *(const float4*)(g_P + ri[w] + kb_n);
                    qq[w] = *(const float4*)(g_Q + rj[w] + kb_n);
                }
            } else {
                #pragma unroll
                for (int w = 0; w < 4; w++) {
                    pp[w] = make_float4(0.f, 0.f, 0.f, 0.f);
                    qq[w] = make_float4(0.f, 0.f, 0.f, 0.f);
                }
            }
            const uint32_t* srcH = g_W2h + (ch + 1) * 768;
            const uint32_t* srcL = g_W2l + (ch + 1) * 768;
            #pragma unroll
            for (int u = 0; u < 3; u++) {
                int w = tid + 256 * u;
                int n = w >> 4, kw = w & 15;
                *(uint32_t*)(nxt + W2H_O + n * RS + kw * 4) = srcH[w];
                *(uint32_t*)(nxt + W2L_O + n * RS + kw * 4) = srcL[w];
            }
        }

        // 2) mma on stage cur
        const uint32_t base = sb + cur * SP_STAGE;
        #pragma unroll
        for (int h = 0; h < 2; h++) {
            const int ks = h * 16;
            uint32_t ah[4], al[4];
            const uint32_t ad = base + (wid * 16 + a_lrow) * RS + (ks + a_lk) * 2;
            LDM_X4(ah[0], ah[1], ah[2], ah[3], ad + AHT_HI);
            LDM_X4(al[0], al[1], al[2], al[3], ad + AHT_LO);
            #pragma unroll
            for (int p = 0; p < 3; p++) {
                const uint32_t bd = base + (p * 16 + b_lrow) * RS + (ks + b_lk) * 2;
                uint32_t bh[4], bl[4];
                LDM_X4(bh[0], bh[1], bh[2], bh[3], bd + W2H_O);
                LDM_X4(bl[0], bl[1], bl[2], bl[3], bd + W2L_O);
                const int nq = (p < 2) ? 2 : 1;
                #pragma unroll
                for (int q = 0; q < 2; q++) {
                    if (q >= nq) break;
                    const int nf = 2 * p + q;
                    mma_bf16(acc[nf], ah, bh[2*q], bh[2*q+1]);
                    mma_bf16(acc[nf], ah, bl[2*q], bl[2*q+1]);
                    mma_bf16(acc[nf], al, bh[2*q], bh[2*q+1]);
                }
            }
        }

        // 3) convert + store Ht of chunk ch+1 into nxt
        if (has_next) {
            float4 c1 = *(const float4*)(ws1c + kb_n);   // zeros past 770
            #pragma unroll
            for (int w = 0; w < 4; w++) {
                int r = g_r0 + w * 32;
                float v0 = fmaxf(fmaf(indv[w], c1.x, pp[w].x + qq[w].x), 0.f);
                float v1 = fmaxf(fmaf(indv[w], c1.y, pp[w].y + qq[w].y), 0.f);
                float v2 = fmaxf(fmaf(indv[w], c1.z, pp[w].z + qq[w].z), 0.f);
                float v3 = fmaxf(fmaf(indv[w], c1.w, pp[w].w + qq[w].w), 0.f);
                uint32_t hw0, lw0, hw1, lw1;
                split2(v0, v1, hw0, lw0);
                split2(v2, v3, hw1, lw1);
                uint32_t ro = r * RS + g_kq * 8;
                *(uint2*)(nxt + AHT_HI + ro) = make_uint2(hw0, hw1);
                *(uint2*)(nxt + AHT_LO + ro) = make_uint2(lw0, lw1);
            }
        }
        __syncthreads();
    }

    float bb[10];
    #pragma unroll
    for (int nf = 0; nf < 5; nf++) {
        bb[2*nf + 0] = bias2[nf * 8 + tig * 2 + 0];
        bb[2*nf + 1] = bias2[nf * 8 + tig * 2 + 1];
    }
    #pragma unroll
    for (int rr = 0; rr < 2; rr++) {
        float l[10];
        #pragma unroll
        for (int nf = 0; nf < 5; nf++) {
            l[2*nf + 0] = acc[nf][2*rr + 0] + bb[2*nf + 0];
            l[2*nf + 1] = acc[nf][2*rr + 1] + bb[2*nf + 1];
        }
        float mx = l[0];
        #pragma unroll
        for (int j = 1; j < 10; j++) mx = fmaxf(mx, l[j]);
        mx = fmaxf(mx, __shfl_xor_sync(0xffffffffu, mx, 1));
        mx = fmaxf(mx, __shfl_xor_sync(0xffffffffu, mx, 2));
        float sm = 0.f;
        #pragma unroll
        for (int j = 0; j < 10; j++) sm += expf(l[j] - mx);
        sm += __shfl_xor_sync(0xffffffffu, sm, 1);
        sm += __shfl_xor_sync(0xffffffffu, sm, 2);
        float lse = mx + logf(sm);

        int p_row = p0 + wid * 16 + grp + 8 * rr;
        if (p_row < NPAIR) {
            float* op = out + ((size_t)b * NPAIR + p_row) * NOUT;
            #pragma unroll
            for (int nf = 0; nf < 5; nf++) {
                float2 v = make_float2(l[2*nf] - lse, l[2*nf + 1] - lse);
                *(float2*)(op + nf * 8 + tig * 2) = v;
            }
        }
    }
}

// ---------------------------------------------------------------------------
// Launch. Inputs (metadata order): hidden_states, pred_spans, token_num,
// span_available_indication_matrix, W1, b1, W2, b2. Output fp32 [16,3405,40].
// ---------------------------------------------------------------------------
extern "C" void kernel_launch(void* const* d_in, const int* in_sizes, int n_in,
                              void* d_out, int out_size) {
    const float* hidden = (const float*)d_in[0];
    const int*   spans  = (const int*)d_in[1];
    const float* W1 = (const float*)d_in[4];
    const float* b1 = (const float*)d_in[5];
    const float* W2 = (const float*)d_in[6];
    const float* b2 = (const float*)d_in[7];
    float* out = (float*)d_out;

    cudaFuncSetAttribute(span_head_tensor,
                         cudaFuncAttributeMaxDynamicSharedMemorySize, SP_DSM);

    prep_all<<<PREP_A_BLKS + PREP_B_BLKS + PREP_W2_BLKS, 256>>>(hidden, W1, W2);
    gemm1_mma<<<dim3(9, (BATCH * SEQL) / 128, 2), 256>>>(b1);
    span_head_tensor<<<dim3(27, BATCH), 256, SP_DSM>>>(W1, b2, spans, out);
}

// round 17
// speedup vs baseline: 1.1769x; 1.1769x over previous
#include <cuda_runtime.h>
#include <cuda_fp16.h>
#include <math.h>
#include <stdint.h>

// Shapes (fixed for this problem)
#define BATCH 16
#define SEQL  128
#define DIM   768
#define NH1   770
#define NOUT  40
#define NPAIR 3405
#define LP1   129     // L+1 rows per batch in hidden_states
#define PST   772     // padded row stride for P/Q (float4-aligned)

// Scratch: P = X @ W1i, Q = X @ W1j (X = hidden[:,1:129,:] flattened, 2048 rows).
__device__ float g_P[(size_t)BATCH * SEQL * PST + 64];
__device__ float g_Q[(size_t)BATCH * SEQL * PST + 64];
// Precomputed fp16 W2 tiles: [chunk(25)][n(48)][kword(16)] (single, no lo).
__device__ uint32_t g_W2h[25 * 768];
// Precomputed split-fp16 A (hidden rows): [row(2048)][kword(384)], hi + lo.
__device__ __align__(16) uint32_t g_Ah[2048 * 384];
__device__ __align__(16) uint32_t g_Al[2048 * 384];
// Precomputed fp16 B (W1 halves, transposed): [z(2)][n(864 pad)][kword(384)].
__device__ __align__(16) uint32_t g_Bh[2 * 864 * 384];

// ---------------------------------------------------------------------------
// Helpers
// ---------------------------------------------------------------------------
__device__ __forceinline__ uint32_t smem_u32(const void* p) {
    uint32_t a;
    asm("{ .reg .u64 t; cvta.to.shared.u64 t, %1; cvt.u32.u64 %0, t; }" : "=r"(a) : "l"(p));
    return a;
}
#define LDM_X4(r0, r1, r2, r3, addr) \
    asm volatile("ldmatrix.sync.aligned.m8n8.x4.shared.b16 {%0,%1,%2,%3}, [%4];" \
                 : "=r"(r0), "=r"(r1), "=r"(r2), "=r"(r3) : "r"(addr))

__device__ __forceinline__ void mma_f16(float* d, const uint32_t* a,
                                        uint32_t b0, uint32_t b1) {
    asm volatile(
        "mma.sync.aligned.m16n8k16.row.col.f32.f16.f16.f32 "
        "{%0,%1,%2,%3}, {%4,%5,%6,%7}, {%8,%9}, {%0,%1,%2,%3};\n"
        : "+f"(d[0]), "+f"(d[1]), "+f"(d[2]), "+f"(d[3])
        : "r"(a[0]), "r"(a[1]), "r"(a[2]), "r"(a[3]), "r"(b0), "r"(b1));
}
// fp16 pack (single) and 2-term split: x = hi + lo, both fp16 RN.
__device__ __forceinline__ uint32_t pack_f16(float x0, float x1) {
    __half2 h = __floats2half2_rn(x0, x1);
    return *reinterpret_cast<uint32_t*>(&h);
}
__device__ __forceinline__ void split2(float x0, float x1, uint32_t& hw, uint32_t& lw) {
    __half2 hp = __floats2half2_rn(x0, x1);
    float l0 = x0 - __low2float(hp);
    float l1 = x1 - __high2float(hp);
    __half2 lp = __floats2half2_rn(l0, l1);
    hw = *reinterpret_cast<uint32_t*>(&hp);
    lw = *reinterpret_cast<uint32_t*>(&lp);
}

// ---------------------------------------------------------------------------
// Kernel 0 (merged prep): block-range dispatch.
//   A: split fp16 hi/lo. B, W2: single fp16.
// ---------------------------------------------------------------------------
#define PREP_A_BLKS  3072
#define PREP_B_BLKS  672
#define PREP_W2_BLKS 75

__global__ void prep_all(const float* __restrict__ hidden,
                         const float* __restrict__ W1,
                         const float* __restrict__ W2) {
    __shared__ float ts[32][65];
    const int blk = blockIdx.x;
    const int tid = threadIdx.x;

    if (blk < PREP_A_BLKS) {
        int idx = blk * 256 + tid;
        int row = idx / 384;
        int kw  = idx - row * 384;
        int bb = row >> 7, t = row & 127;
        const float* src = hidden + ((size_t)bb * LP1 + t + 1) * DIM + kw * 2;
        float2 v = *(const float2*)src;
        uint32_t hw, lw;
        split2(v.x, v.y, hw, lw);
        g_Ah[idx] = hw;
        g_Al[idx] = lw;
    } else if (blk < PREP_A_BLKS + PREP_B_BLKS) {
        int bid = blk - PREP_A_BLKS;
        int z   = bid / 336;
        int t2  = bid - z * 336;
        int kt  = t2 % 24;
        int nt  = t2 / 24;
        int k0  = kt * 32;
        int n0  = nt * 64;
        const float* W = W1 + (size_t)z * DIM * NH1;

        int nx = tid & 63;
        int ky0 = tid >> 6;
        #pragma unroll
        for (int s = 0; s < 8; s++) {
            int ky = ky0 + 4 * s;
            int n  = n0 + nx;
            ts[ky][nx] = (n < NH1) ? W[(size_t)(k0 + ky) * NH1 + n] : 0.f;
        }
        __syncthreads();
        int kx  = tid & 15;
        int ny0 = tid >> 4;
        #pragma unroll
        for (int s = 0; s < 4; s++) {
            int ny = ny0 + 16 * s;
            int n  = n0 + ny;
            if (n < 864) {
                size_t gidx = ((size_t)z * 864 + n) * 384 + kt * 16 + kx;
                g_Bh[gidx] = pack_f16(ts[2*kx][ny], ts[2*kx+1][ny]);
            }
        }
    } else {
        int idx = (blk - PREP_A_BLKS - PREP_B_BLKS) * 256 + tid;
        if (idx >= 25 * 768) return;
        int ch = idx / 768, rem = idx - ch * 768;
        int n = rem >> 4, kw = rem & 15;
        int k = ch * 32 + kw * 2;
        float x0 = 0.f, x1 = 0.f;
        if (n < NOUT) {
            if (k     < NH1) x0 = W2[(size_t)k       * NOUT + n];
            if (k + 1 < NH1) x1 = W2[(size_t)(k + 1) * NOUT + n];
        }
        g_W2h[idx] = pack_f16(x0, x1);
    }
}

// ---------------------------------------------------------------------------
// Kernel 1: 2048 x 864(pad of 770) x 768 GEMM, fp16 m16n8k16 + ldmatrix,
// 2-term split (A hi/lo, B single). z=0 -> P, z=1 -> Q.
// Block 128(M) x 96(N), 256 thr = 8 warps (4M x 2N), warp tile 32x48, BK=32.
// Grid = 9*16*2 = 288 blocks at occ 2 -> one balanced wave.
// ---------------------------------------------------------------------------
#define G_BK  32
#define G_NKT (DIM / G_BK)   // 24
#define RS    80             // smem row stride in bytes
#define AHI_O 0
#define ALO_O (128 * RS)     // 10240
#define BHI_O (2 * 128 * RS) // 20480; total 28160 B

__global__ __launch_bounds__(256, 2)
void gemm1_mma(void) {
    __shared__ __align__(16) unsigned char smbuf[BHI_O + 96 * RS];
    const uint32_t sb = smem_u32(smbuf);

    const int tid = threadIdx.x;
    const int wid = tid >> 5;
    const int lid = tid & 31;
    const int grp = lid >> 2;
    const int tig = lid & 3;
    const int wm  = wid & 3;    // warp M index (32 rows)
    const int wn  = wid >> 2;   // warp N index (48 cols)

    const int n0 = blockIdx.x * 96;
    const int m0 = blockIdx.y * 128;
    const int z  = blockIdx.z;
    float* Cout = (z == 0) ? g_P : g_Q;

    float acc[2][6][4];
    #pragma unroll
    for (int mf = 0; mf < 2; mf++)
        #pragma unroll
        for (int nf = 0; nf < 6; nf++)
            #pragma unroll
            for (int c = 0; c < 4; c++) acc[mf][nf][c] = 0.f;

    const int a_q = tid & 3;
    const int a_r = tid >> 2;
    const int b_w8 = tid & 7;
    const int b_r  = tid >> 3;
    const size_t bbase = ((size_t)z * 864 + n0) * 384;

    const int a_lrow = lid & 15;
    const int a_lk   = (lid >> 4) << 3;
    const int b_lrow = (lid & 7) + ((lid >> 4) << 3);
    const int b_lk   = ((lid >> 3) & 1) << 3;

    for (int kt = 0; kt < G_NKT; kt++) {
        const int kw0 = kt * 16;
        #pragma unroll
        for (int p = 0; p < 2; p++) {
            const int row = a_r + 64 * p;
            const size_t gidx = (size_t)(m0 + row) * 384 + kw0 + a_q * 4;
            uint4 h = *(const uint4*)(g_Ah + gidx);
            uint4 l = *(const uint4*)(g_Al + gidx);
            *(uint4*)(smbuf + AHI_O + row * RS + a_q * 16) = h;
            *(uint4*)(smbuf + ALO_O + row * RS + a_q * 16) = l;
        }
        #pragma unroll
        for (int p = 0; p < 3; p++) {
            const int row = b_r + 32 * p;
            const size_t gidx = bbase + (size_t)row * 384 + kw0 + b_w8 * 2;
            uint2 h = *(const uint2*)(g_Bh + gidx);
            *(uint2*)(smbuf + BHI_O + row * RS + b_w8 * 8) = h;
        }
        __syncthreads();

        #pragma unroll
        for (int h = 0; h < 2; h++) {
            const int ks = h * 16;
            uint32_t ah[2][4], al[2][4];
            #pragma unroll
            for (int mf = 0; mf < 2; mf++) {
                const uint32_t ad = sb + (wm * 32 + mf * 16 + a_lrow) * RS
                                       + (ks + a_lk) * 2;
                LDM_X4(ah[mf][0], ah[mf][1], ah[mf][2], ah[mf][3], ad + AHI_O);
                LDM_X4(al[mf][0], al[mf][1], al[mf][2], al[mf][3], ad + ALO_O);
            }
            #pragma unroll
            for (int p = 0; p < 3; p++) {
                const uint32_t bd = sb + (wn * 48 + p * 16 + b_lrow) * RS
                                       + (ks + b_lk) * 2;
                uint32_t bh[4];
                LDM_X4(bh[0], bh[1], bh[2], bh[3], bd + BHI_O);
                #pragma unroll
                for (int q = 0; q < 2; q++) {
                    const int nf = 2 * p + q;
                    #pragma unroll
                    for (int mf = 0; mf < 2; mf++) {
                        mma_f16(acc[mf][nf], ah[mf], bh[2*q], bh[2*q+1]);
                        mma_f16(acc[mf][nf], al[mf], bh[2*q], bh[2*q+1]);
                    }
                }
            }
        }
        __syncthreads();
    }

    // Epilogue: d0,d1 -> (row, 2*tig..+1); d2,d3 -> (row+8, ...).
    // B cols >= 770 were prepped as zeros -> pad cols 770/771 get zeros.
    #pragma unroll
    for (int mf = 0; mf < 2; mf++) {
        const int row = m0 + wm * 32 + mf * 16 + grp;
        #pragma unroll
        for (int nf = 0; nf < 6; nf++) {
            const int nn = n0 + wn * 48 + nf * 8 + tig * 2;
            if (nn + 1 < PST) {
                float* p0 = Cout + (size_t)row * PST + nn;
                float* p1 = Cout + (size_t)(row + 8) * PST + nn;
                *(float2*)p0 = make_float2(acc[mf][nf][0], acc[mf][nf][1]);
                *(float2*)p1 = make_float2(acc[mf][nf][2], acc[mf][nf][3]);
            }
        }
    }
}

// ---------------------------------------------------------------------------
// Kernel 2 (R12 skeleton, fp16 2-term): tensorized span head, double-buffered.
// Ht = relu(P[vi]+Q[vj]+ind*w1c+b1) split fp16 hi/lo; W2 single fp16;
// logits = Ht_hi @ W2 + Ht_lo @ W2 + b2; fused log_softmax.
// ---------------------------------------------------------------------------
#define SP_NCH   25
#define AHT_HI   0
#define AHT_LO   10240
#define W2H_O    20480
#define SP_STAGE 24320                 // 128*80*2 + 48*80
#define WS1C_O   (2 * SP_STAGE)        // 48640
#define SB1_O    (WS1C_O + 832 * 4)    // 51968
#define SRI_O    (SB1_O + 832 * 4)     // 55296
#define SRJ_O    (SRI_O + 512)
#define SIND_O   (SRJ_O + 512)
#define SP_DSM   (SIND_O + 512)        // 56832

__global__ __launch_bounds__(256, 2)
void span_head_tensor(const float* __restrict__ W1, const float* __restrict__ bias1,
                      const float* __restrict__ bias2,
                      const int* __restrict__ spans, float* __restrict__ out) {
    extern __shared__ __align__(16) unsigned char dsm[];
    const uint32_t sb = smem_u32(dsm);
    float* ws1c = (float*)(dsm + WS1C_O);
    float* sb1  = (float*)(dsm + SB1_O);
    int*   s_ri = (int*)(dsm + SRI_O);
    int*   s_rj = (int*)(dsm + SRJ_O);
    float* s_in = (float*)(dsm + SIND_O);

    const int b   = blockIdx.y;
    const int p0  = blockIdx.x * 128;
    const int tid = threadIdx.x;
    const int wid = tid >> 5;
    const int lid = tid & 31;
    const int grp = lid >> 2;
    const int tig = lid & 3;

    const float* w1c = W1 + (size_t)2 * DIM * NH1;

    for (int idx = tid; idx < 832; idx += 256) {
        ws1c[idx] = (idx < NH1) ? w1c[idx]   : 0.f;
        sb1[idx]  = (idx < NH1) ? bias1[idx] : 0.f;
    }
    if (tid < 128) {
        int p  = p0 + tid;
        int pc = (p < NPAIR) ? p : (NPAIR - 1);
        int i, j;
        if (pc < 2970) {
            i = pc / 30;
            j = i + (pc - 30 * i);
        } else {
            int q = pc - 2970;
            int d = (int)(29.5f - sqrtf(870.25f - 2.0f * (float)q));
            while ((d + 1) * (58 - d) / 2 <= q) d++;
            while (d * (59 - d) / 2 > q) d--;
            i = 99 + d;
            j = i + (q - d * (59 - d) / 2);
        }
        float ind = 0.f;
        if (p < NPAIR) {
            int s = spans[b*2 + 0];
            int e = spans[b*2 + 1];
            if (i == s && j == e)      ind = 2.f;
            else if (i >= s && j <= e) ind = 1.f;
        }
        s_ri[tid] = (b * SEQL + i) * PST;
        s_rj[tid] = (b * SEQL + j) * PST;
        s_in[tid] = ind;
    }
    __syncthreads();

    const int g_kq = tid & 7;
    const int g_r0 = tid >> 3;
    int   ri[4], rj[4];
    float indv[4];
    #pragma unroll
    for (int w = 0; w < 4; w++) {
        int r = g_r0 + w * 32;
        ri[w] = s_ri[r]; rj[w] = s_rj[r]; indv[w] = s_in[r];
    }

    const int a_lrow = lid & 15;
    const int a_lk   = (lid >> 4) << 3;
    const int b_lrow = (lid & 7) + ((lid >> 4) << 3);
    const int b_lk   = ((lid >> 3) & 1) << 3;

    float acc[5][4];
    #pragma unroll
    for (int nf = 0; nf < 5; nf++)
        #pragma unroll
        for (int c = 0; c < 4; c++) acc[nf][c] = 0.f;

    {   // prologue: stage 0 (chunk 0)
        const int kb = g_kq * 4;
        float4 c1 = *(const float4*)(ws1c + kb);
        float4 c2 = *(const float4*)(sb1 + kb);
        #pragma unroll
        for (int w = 0; w < 4; w++) {
            int r = g_r0 + w * 32;
            float4 p4 = *(const float4*)(g_P + ri[w] + kb);
            float4 q4 = *(const float4*)(g_Q + rj[w] + kb);
            float v0 = fmaxf(fmaf(indv[w], c1.x, p4.x + q4.x + c2.x), 0.f);
            float v1 = fmaxf(fmaf(indv[w], c1.y, p4.y + q4.y + c2.y), 0.f);
            float v2 = fmaxf(fmaf(indv[w], c1.z, p4.z + q4.z + c2.z), 0.f);
            float v3 = fmaxf(fmaf(indv[w], c1.w, p4.w + q4.w + c2.w), 0.f);
            uint32_t hw0, lw0, hw1, lw1;
            split2(v0, v1, hw0, lw0);
            split2(v2, v3, hw1, lw1);
            uint32_t ro = r * RS + g_kq * 8;
            *(uint2*)(dsm + AHT_HI + ro) = make_uint2(hw0, hw1);
            *(uint2*)(dsm + AHT_LO + ro) = make_uint2(lw0, lw1);
        }
        #pragma unroll
        for (int u = 0; u < 3; u++) {
            int w = tid + 256 * u;
            int n = w >> 4, kw = w & 15;
            *(uint32_t*)(dsm + W2H_O + n * RS + kw * 4) = g_W2h[w];
        }
    }
    __syncthreads();

    for (int ch = 0; ch < SP_NCH; ch++) {
        const int cur = ch & 1;
        const bool has_next = (ch + 1 < SP_NCH);
        const int kb_n = (ch + 1) * 32 + g_kq * 4;
        unsigned char* nxt = dsm + ((ch + 1) & 1) * SP_STAGE;

        // 1) prefetch chunk ch+1: P/Q into regs; W2 LDG->STS into nxt (safe:
        //    prior barrier retired all reads of nxt).
        float4 pp[4], qq[4];
        if (has_next) {
            if (kb_n < PST) {
                #pragma unroll
                for (int w = 0; w < 4; w++) {
                    pp[w] = *(const float4*)(g_P + ri[w] + kb_n);
                    qq[w] = *(const float4*)(g_Q + rj[w] + kb_n);
                }
            } else {
                #pragma unroll
                for (int w = 0; w < 4; w++) {
                    pp[w] = make_float4(0.f, 0.f, 0.f, 0.f);
                    qq[w] = make_float4(0.f, 0.f, 0.f, 0.f);
                }
            }
            const uint32_t* srcH = g_W2h + (ch + 1) * 768;
            #pragma unroll
            for (int u = 0; u < 3; u++) {
                int w = tid + 256 * u;
                int n = w >> 4, kw = w & 15;
                *(uint32_t*)(nxt + W2H_O + n * RS + kw * 4) = srcH[w];
            }
        }

        // 2) mma on stage cur (2 terms)
        const uint32_t base = sb + cur * SP_STAGE;
        #pragma unroll
        for (int h = 0; h < 2; h++) {
            const int ks = h * 16;
            uint32_t ah[4], al[4];
            const uint32_t ad = base + (wid * 16 + a_lrow) * RS + (ks + a_lk) * 2;
            LDM_X4(ah[0], ah[1], ah[2], ah[3], ad + AHT_HI);
            LDM_X4(al[0], al[1], al[2], al[3], ad + AHT_LO);
            #pragma unroll
            for (int p = 0; p < 3; p++) {
                const uint32_t bd = base + (p * 16 + b_lrow) * RS + (ks + b_lk) * 2;
                uint32_t bh[4];
                LDM_X4(bh[0], bh[1], bh[2], bh[3], bd + W2H_O);
                const int nq = (p < 2) ? 2 : 1;
                #pragma unroll
                for (int q = 0; q < 2; q++) {
                    if (q >= nq) break;
                    const int nf = 2 * p + q;
                    mma_f16(acc[nf], ah, bh[2*q], bh[2*q+1]);
                    mma_f16(acc[nf], al, bh[2*q], bh[2*q+1]);
                }
            }
        }

        // 3) convert + store Ht of chunk ch+1 into nxt
        if (has_next) {
            float4 c1 = *(const float4*)(ws1c + kb_n);   // zeros past 770
            float4 c2 = *(const float4*)(sb1 + kb_n);
            #pragma unroll
            for (int w = 0; w < 4; w++) {
                int r = g_r0 + w * 32;
                float v0 = fmaxf(fmaf(indv[w], c1.x, pp[w].x + qq[w].x + c2.x), 0.f);
                float v1 = fmaxf(fmaf(indv[w], c1.y, pp[w].y + qq[w].y + c2.y), 0.f);
                float v2 = fmaxf(fmaf(indv[w], c1.z, pp[w].z + qq[w].z + c2.z), 0.f);
                float v3 = fmaxf(fmaf(indv[w], c1.w, pp[w].w + qq[w].w + c2.w), 0.f);
                uint32_t hw0, lw0, hw1, lw1;
                split2(v0, v1, hw0, lw0);
                split2(v2, v3, hw1, lw1);
                uint32_t ro = r * RS + g_kq * 8;
                *(uint2*)(nxt + AHT_HI + ro) = make_uint2(hw0, hw1);
                *(uint2*)(nxt + AHT_LO + ro) = make_uint2(lw0, lw1);
            }
        }
        __syncthreads();
    }

    float bb[10];
    #pragma unroll
    for (int nf = 0; nf < 5; nf++) {
        bb[2*nf + 0] = bias2[nf * 8 + tig * 2 + 0];
        bb[2*nf + 1] = bias2[nf * 8 + tig * 2 + 1];
    }
    #pragma unroll
    for (int rr = 0; rr < 2; rr++) {
        float l[10];
        #pragma unroll
        for (int nf = 0; nf < 5; nf++) {
            l[2*nf + 0] = acc[nf][2*rr + 0] + bb[2*nf + 0];
            l[2*nf + 1] = acc[nf][2*rr + 1] + bb[2*nf + 1];
        }
        float mx = l[0];
        #pragma unroll
        for (int j = 1; j < 10; j++) mx = fmaxf(mx, l[j]);
        mx = fmaxf(mx, __shfl_xor_sync(0xffffffffu, mx, 1));
        mx = fmaxf(mx, __shfl_xor_sync(0xffffffffu, mx, 2));
        float sm = 0.f;
        #pragma unroll
        for (int j = 0; j < 10; j++) sm += expf(l[j] - mx);
        sm += __shfl_xor_sync(0xffffffffu, sm, 1);
        sm += __shfl_xor_sync(0xffffffffu, sm, 2);
        float lse = mx + logf(sm);

        int p_row = p0 + wid * 16 + grp + 8 * rr;
        if (p_row < NPAIR) {
            float* op = out + ((size_t)b * NPAIR + p_row) * NOUT;
            #pragma unroll
            for (int nf = 0; nf < 5; nf++) {
                float2 v = make_float2(l[2*nf] - lse, l[2*nf + 1] - lse);
                *(float2*)(op + nf * 8 + tig * 2) = v;
            }
        }
    }
}

// ---------------------------------------------------------------------------
// Launch. Inputs (metadata order): hidden_states, pred_spans, token_num,
// span_available_indication_matrix, W1, b1, W2, b2. Output fp32 [16,3405,40].
// ---------------------------------------------------------------------------
extern "C" void kernel_launch(void* const* d_in, const int* in_sizes, int n_in,
                              void* d_out, int out_size) {
    const float* hidden = (const float*)d_in[0];
    const int*   spans  = (const int*)d_in[1];
    const float* W1 = (const float*)d_in[4];
    const float* b1 = (const float*)d_in[5];
    const float* W2 = (const float*)d_in[6];
    const float* b2 = (const float*)d_in[7];
    float* out = (float*)d_out;

    cudaFuncSetAttribute(span_head_tensor,
                         cudaFuncAttributeMaxDynamicSharedMemorySize, SP_DSM);

    prep_all<<<PREP_A_BLKS + PREP_B_BLKS + PREP_W2_BLKS, 256>>>(hidden, W1, W2);
    gemm1_mma<<<dim3(9, (BATCH * SEQL) / 128, 2), 256>>>();
    span_head_tensor<<<dim3(27, BATCH), 256, SP_DSM>>>(W1, b1, b2, spans, out);
}